// round 2
// baseline (speedup 1.0000x reference)
#include <cuda_runtime.h>

#define N_AGENTS 11
#define OBS_DIM 115
#define GS_DIM (N_AGENTS * OBS_DIM)   // 1265
#define ID_LO 97

__global__ __launch_bounds__(256, 8)
void qllmmixer_kernel(const float* __restrict__ q,        // [B, 11]
                      const float* __restrict__ gs,       // [B, 1265]
                      float* __restrict__ out,            // [B]
                      int B)
{
    const int gtid = blockIdx.x * blockDim.x + threadIdx.x;
    const int row  = gtid >> 5;
    const int lane = gtid & 31;
    if (row >= B) return;

    const float* grow = gs + (long long)row * GS_DIM;

    // Broadcast scalars: every lane loads the same address -> HW broadcast.
    const float bx   = __ldg(grow + 88);
    const float by   = __ldg(grow + 89);
    const float team = __ldg(grow + 95);

    // ball-goal distance (goal = (1, 0))
    const float dxg = bx - 1.0f;
    const float bgd = sqrtf(dxg * dxg + by * by);
    const bool valid = (team != 0.0f) && (bgd > 0.19f) && (bgd < 0.99f);

    const float POS_INF = __int_as_float(0x7f800000);
    const float NEG_INF = __int_as_float(0xff800000);

    float dist   = POS_INF;
    float gd     = 0.0f;
    float qa     = 0.0f;
    int   my_idx = 64;   // worse than any real agent index for argmin tie-break

    if (lane < N_AGENTS) {
        const float* arow = grow + lane * OBS_DIM;

        // argmax over obs[lane, 97:108] — strict '>' gives first-max (jnp.argmax)
        float best = __ldg(arow + ID_LO);
        int   bid  = 0;
        #pragma unroll
        for (int k = 1; k < N_AGENTS; ++k) {
            float v = __ldg(arow + ID_LO + k);
            if (v > best) { best = v; bid = k; }
        }

        const float px = __ldg(arow + 2 * bid);
        const float py = __ldg(arow + 2 * bid + 1);

        const float dxb = px - bx;
        const float dyb = py - by;
        dist = sqrtf(dxb * dxb + dyb * dyb);

        const float dxgl = px - 1.0f;
        gd = sqrtf(dxgl * dxgl + py * py);

        qa = __ldg(q + (long long)row * N_AGENTS + lane);
        my_idx = lane;
    }

    // warp argmin over dist with first-index tie-break (jnp.argmin)
    float mval = dist;
    int   midx = my_idx;
    #pragma unroll
    for (int off = 16; off > 0; off >>= 1) {
        float ov = __shfl_xor_sync(0xFFFFFFFFu, mval, off);
        int   oi = __shfl_xor_sync(0xFFFFFFFFu, midx, off);
        if (ov < mval || (ov == mval && oi < midx)) { mval = ov; midx = oi; }
    }

    // combined value per agent
    float combined;
    if (lane < N_AGENTS) {
        if (valid) {
            combined = (lane == midx) ? 5.0f : 0.0f;
        } else {
            combined = 1.0f / (gd + 1e-6f);
        }
    } else {
        combined = NEG_INF;
    }

    // stable softmax over the 11 agents (lanes >= 11 contribute nothing)
    float m = combined;
    #pragma unroll
    for (int off = 16; off > 0; off >>= 1)
        m = fmaxf(m, __shfl_xor_sync(0xFFFFFFFFu, m, off));

    float e = (lane < N_AGENTS) ? expf(combined - m) : 0.0f;

    float s  = e;
    float qe = qa * e;
    #pragma unroll
    for (int off = 16; off > 0; off >>= 1) {
        s  += __shfl_xor_sync(0xFFFFFFFFu, s,  off);
        qe += __shfl_xor_sync(0xFFFFFFFFu, qe, off);
    }

    if (lane == 0)
        out[row] = (qe / s) * (float)N_AGENTS;
}

extern "C" void kernel_launch(void* const* d_in, const int* in_sizes, int n_in,
                              void* d_out, int out_size)
{
    const float* q  = (const float*)d_in[0];   // agents_q  [128,512,11]
    const float* gs = (const float*)d_in[1];   // global_state [128,512,1265]
    float* out = (float*)d_out;

    const int B = in_sizes[0] / N_AGENTS;      // 65536 rows

    const int threads = 256;                   // 8 warps = 8 rows per block
    const int rows_per_block = threads / 32;
    const int blocks = (B + rows_per_block - 1) / rows_per_block;

    qllmmixer_kernel<<<blocks, threads>>>(q, gs, out, B);
}

// round 3
// speedup vs baseline: 1.0432x; 1.0432x over previous
#include <cuda_runtime.h>

#define N_AGENTS 11
#define OBS_DIM 115
#define GS_DIM (N_AGENTS * OBS_DIM)   // 1265
#define ID_LO 97

__global__ __launch_bounds__(256, 8)
void qllmmixer_kernel(const float* __restrict__ q,        // [B, 11]
                      const float* __restrict__ gs,       // [B, 1265]
                      float* __restrict__ out,            // [B]
                      int B)
{
    const int gtid = blockIdx.x * blockDim.x + threadIdx.x;
    const int row  = gtid >> 5;
    const int lane = gtid & 31;
    if (row >= B) return;

    const float POS_INF = __int_as_float(0x7f800000);
    const float NEG_INF = __int_as_float(0xff800000);

    const float* grow = gs + (long long)row * GS_DIM;

    // Broadcast scalars (all lanes same address -> 1 wavefront)
    const float bx   = __ldg(grow + 88);
    const float by   = __ldg(grow + 89);
    const float team = __ldg(grow + 95);

    const float dxg = bx - 1.0f;
    const float bgd = sqrtf(dxg * dxg + by * by);
    const bool valid = (team != 0.0f) && (bgd > 0.19f) && (bgd < 0.99f);

    // Two lanes per agent: lane = 2*agent + half, agents 0..10 on lanes 0..21.
    const int  agent = lane >> 1;
    const int  half  = lane & 1;
    const bool act   = (lane < 2 * N_AGENTS);

    const float* arow = grow + agent * OBS_DIM;   // valid ptr arithmetic even if unused

    // ---- Split argmax over obs[agent, 97:108] (11 values: half0 k=0..5, half1 k=6..10)
    const int k0 = half ? 6 : 0;
    const int kn = half ? 5 : 6;

    float v[6];
    #pragma unroll
    for (int j = 0; j < 6; ++j) {
        v[j] = (act && j < kn) ? __ldg(arow + ID_LO + k0 + j) : NEG_INF;
    }

    // local argmax, strict '>' keeps first occurrence
    float mb = v[0];
    int   mi = k0;
    #pragma unroll
    for (int j = 1; j < 6; ++j) {
        if (v[j] > mb) { mb = v[j]; mi = k0 + j; }
    }

    // combine the pair; h0 (lower indices) wins ties -> jnp.argmax semantics
    const float ob = __shfl_xor_sync(0xFFFFFFFFu, mb, 1);
    const int   oi = __shfl_xor_sync(0xFFFFFFFFu, mi, 1);
    const float b0 = half ? ob : mb;
    const int   i0 = half ? oi : mi;
    const float b1 = half ? mb : ob;
    const int   i1 = half ? mi : oi;
    const int   bid = (b0 >= b1) ? i0 : i1;

    // ---- Split pos gather: even lane loads px, odd lane loads py
    float mypos = 0.0f;
    if (act) mypos = __ldg(arow + 2 * bid + half);
    const float otherpos = __shfl_xor_sync(0xFFFFFFFFu, mypos, 1);

    // ---- Per-agent values live on even active lanes
    float dist = POS_INF;
    float gd   = 0.0f;
    float qa   = 0.0f;
    int   aidx = 64;

    if (act && half == 0) {
        const float px = mypos;
        const float py = otherpos;

        const float dxb = px - bx;
        const float dyb = py - by;
        dist = sqrtf(dxb * dxb + dyb * dyb);

        const float dxgl = px - 1.0f;
        gd = sqrtf(dxgl * dxgl + py * py);

        qa = __ldg(q + (long long)row * N_AGENTS + agent);
        aidx = agent;
    }

    // ---- warp argmin over dist, first-index tie-break (jnp.argmin)
    float mval = dist;
    int   midx = aidx;
    #pragma unroll
    for (int off = 16; off > 0; off >>= 1) {
        float ov = __shfl_xor_sync(0xFFFFFFFFu, mval, off);
        int   oi2 = __shfl_xor_sync(0xFFFFFFFFu, midx, off);
        if (ov < mval || (ov == mval && oi2 < midx)) { mval = ov; midx = oi2; }
    }

    // ---- combined value per agent (even active lanes), softmax over 11 agents
    float combined = NEG_INF;
    if (act && half == 0) {
        if (valid) combined = (aidx == midx) ? 5.0f : 0.0f;
        else       combined = 1.0f / (gd + 1e-6f);
    }

    float m = combined;
    #pragma unroll
    for (int off = 16; off > 0; off >>= 1)
        m = fmaxf(m, __shfl_xor_sync(0xFFFFFFFFu, m, off));

    const float e = (act && half == 0) ? expf(combined - m) : 0.0f;

    float s  = e;
    float qe = qa * e;
    #pragma unroll
    for (int off = 16; off > 0; off >>= 1) {
        s  += __shfl_xor_sync(0xFFFFFFFFu, s,  off);
        qe += __shfl_xor_sync(0xFFFFFFFFu, qe, off);
    }

    if (lane == 0)
        out[row] = (qe / s) * (float)N_AGENTS;
}

extern "C" void kernel_launch(void* const* d_in, const int* in_sizes, int n_in,
                              void* d_out, int out_size)
{
    const float* q  = (const float*)d_in[0];   // agents_q  [128,512,11]
    const float* gs = (const float*)d_in[1];   // global_state [128,512,1265]
    float* out = (float*)d_out;

    const int B = in_sizes[0] / N_AGENTS;      // 65536 rows

    const int threads = 256;                   // 8 warps = 8 rows per block
    const int rows_per_block = threads / 32;
    const int blocks = (B + rows_per_block - 1) / rows_per_block;

    qllmmixer_kernel<<<blocks, threads>>>(q, gs, out, B);
}

// round 5
// speedup vs baseline: 1.1059x; 1.0601x over previous
#include <cuda_runtime.h>

#define N_AGENTS 11
#define OBS_DIM 115
#define GS_DIM (N_AGENTS * OBS_DIM)   // 1265
#define ID_LO 97
#define FULL 0xFFFFFFFFu

__global__ __launch_bounds__(256, 8)
void qllmmixer_kernel(const float* __restrict__ q,        // [B, 11]
                      const float* __restrict__ gs,       // [B, 1265]
                      float* __restrict__ out,            // [B]
                      int B)
{
    const int warp_id = (blockIdx.x * blockDim.x + threadIdx.x) >> 5;
    const int lane    = threadIdx.x & 31;
    const int halfw   = lane >> 4;          // which row within the warp
    const int sub     = lane & 15;          // lane within the half-warp

    const long long row = (long long)warp_id * 2 + halfw;
    const bool rowok = row < (long long)B;

    const float POS_INF = __int_as_float(0x7f800000);
    const float NEG_INF = __int_as_float(0xff800000);

    const float* grow = gs + row * GS_DIM;

    // Per-half broadcast scalars (16 lanes, same address -> broadcast wavefront)
    float bx = 0.f, by = 0.f, team = 0.f;
    if (rowok) {
        bx   = __ldg(grow + 88);
        by   = __ldg(grow + 89);
        team = __ldg(grow + 95);
    }

    const float dxg = bx - 1.0f;
    const float bgd = sqrtf(dxg * dxg + by * by);
    const bool valid = (team != 0.0f) && (bgd > 0.19f) && (bgd < 0.99f);

    // One lane per agent within the half-warp
    const bool act = rowok && (sub < N_AGENTS);
    // Clamp inactive lanes onto agent 0 so their (unused) loads are in-bounds
    // broadcast duplicates rather than OOB.
    const int agent = (sub < N_AGENTS) ? sub : 0;
    const float* arow = grow + agent * OBS_DIM;

    // ---- id window obs[agent, 97:108): 11 scalar loads, front-batched.
    // (No vectorization possible: row stride 1265 ≡ 1 mod 4 breaks alignment.)
    float v[N_AGENTS];
    if (rowok) {
        #pragma unroll
        for (int k = 0; k < N_AGENTS; ++k)
            v[k] = __ldcs(arow + ID_LO + k);     // streamed once, evict-first
    } else {
        #pragma unroll
        for (int k = 0; k < N_AGENTS; ++k)
            v[k] = 0.0f;
    }

    // argmax, strict '>' keeps first occurrence (jnp.argmax)
    float best = v[0];
    int   bid  = 0;
    #pragma unroll
    for (int k = 1; k < N_AGENTS; ++k)
        if (v[k] > best) { best = v[k]; bid = k; }

    // ---- dependent pos gather (scalar: 8B alignment not guaranteed)
    float px = 0.0f, py = 0.0f, qa = 0.0f;
    if (rowok) {
        px = __ldcs(arow + 2 * bid);
        py = __ldcs(arow + 2 * bid + 1);
        qa = __ldg(q + row * N_AGENTS + agent);
    }

    float dist = POS_INF;
    float gd   = 0.0f;
    int   aidx = 64;

    if (act) {
        const float dxb = px - bx;
        const float dyb = py - by;
        dist = sqrtf(dxb * dxb + dyb * dyb);

        const float dxgl = px - 1.0f;
        gd = sqrtf(dxgl * dxgl + py * py);

        aidx = sub;
    } else {
        qa = 0.0f;
    }

    // ---- half-warp argmin over dist, first-index tie-break (jnp.argmin)
    float mval = dist;
    int   midx = aidx;
    #pragma unroll
    for (int off = 8; off > 0; off >>= 1) {
        float ov = __shfl_xor_sync(FULL, mval, off);
        int   oi = __shfl_xor_sync(FULL, midx, off);
        if (ov < mval || (ov == mval && oi < midx)) { mval = ov; midx = oi; }
    }

    // ---- combined value, softmax over the 11 agents of this half
    float combined = NEG_INF;
    if (act) {
        if (valid) combined = (aidx == midx) ? 5.0f : 0.0f;
        else       combined = 1.0f / (gd + 1e-6f);
    }

    float m = combined;
    #pragma unroll
    for (int off = 8; off > 0; off >>= 1)
        m = fmaxf(m, __shfl_xor_sync(FULL, m, off));

    const float e = act ? expf(combined - m) : 0.0f;

    float s  = e;
    float qe = qa * e;
    #pragma unroll
    for (int off = 8; off > 0; off >>= 1) {
        s  += __shfl_xor_sync(FULL, s,  off);
        qe += __shfl_xor_sync(FULL, qe, off);
    }

    if (sub == 0 && rowok)
        out[row] = (qe / s) * (float)N_AGENTS;
}

extern "C" void kernel_launch(void* const* d_in, const int* in_sizes, int n_in,
                              void* d_out, int out_size)
{
    const float* q  = (const float*)d_in[0];   // agents_q  [128,512,11]
    const float* gs = (const float*)d_in[1];   // global_state [128,512,1265]
    float* out = (float*)d_out;

    const int B = in_sizes[0] / N_AGENTS;      // 65536 rows

    const int threads = 256;                   // 8 warps = 16 rows per block
    const int rows_per_block = (threads / 32) * 2;
    const int blocks = (B + rows_per_block - 1) / rows_per_block;

    qllmmixer_kernel<<<blocks, threads>>>(q, gs, out, B);
}